// round 1
// baseline (speedup 1.0000x reference)
#include <cuda_runtime.h>

#define NPIX 4096
#define CIN  512
#define DK   64
#define BAT  4

// ---------------- scratch (device globals; no runtime allocation) ----------------
__device__ float g_q[BAT * DK * NPIX];
__device__ float g_k[BAT * DK * NPIX];
__device__ float g_v[BAT * CIN * NPIX];
__device__ float g_p[BAT * DK * NPIX];          // xd
__device__ float g_cf[BAT * DK * NPIX];         // gamma_c * c_out + xd
__device__ float g_attn[(size_t)BAT * NPIX * NPIX];   // 256 MB: energy, then attn in-place
__device__ float g_Wall[704 * 512];
__device__ float g_ball[704];
__device__ float g_epart[8 * BAT * DK * DK];    // channel-e partials (no atomics)
__device__ float g_cattn[BAT * DK * DK];

// ---------------- weight packing: [Wq;Wk;Wv;Wd] -> 704x512 ----------------
__global__ void pack_kernel(const float* __restrict__ Wq, const float* __restrict__ bq,
                            const float* __restrict__ Wk, const float* __restrict__ bk,
                            const float* __restrict__ Wv, const float* __restrict__ bv,
                            const float* __restrict__ Wd, const float* __restrict__ bd) {
    int i = blockIdx.x * blockDim.x + threadIdx.x;
    if (i < 704 * 512) {
        int o = i >> 9, c = i & 511;
        float v;
        if (o < 64)        v = Wq[o * 512 + c];
        else if (o < 128)  v = Wk[(o - 64) * 512 + c];
        else if (o < 640)  v = Wv[(o - 128) * 512 + c];
        else               v = Wd[(o - 640) * 512 + c];
        g_Wall[i] = v;
    }
    if (i < 704) {
        float v;
        if (i < 64)        v = bq[i];
        else if (i < 128)  v = bk[i - 64];
        else if (i < 640)  v = bv[i - 128];
        else               v = bd[i - 640];
        g_ball[i] = v;
    }
}

// ---------------- projection GEMM: out[o,n] = Wall[o,:] . x[b,:,n] + ball[o] ----------------
// A = Wall [704][512] (K-contiguous), B = x[b] [512][4096] (K-major, n contiguous)
__global__ __launch_bounds__(256) void proj_kernel(const float* __restrict__ x) {
    int b = blockIdx.z;
    int n0 = blockIdx.x * 128;
    int o0 = blockIdx.y * 128;
    const float* B = x + (size_t)b * CIN * NPIX;

    __shared__ float As[8][128];
    __shared__ float Bs[8][128];
    int t = threadIdx.x;
    float acc[8][8] = {};
    int arow = t >> 1, akq = (t & 1) * 4;
    int bk = t >> 5, bnq = (t & 31) * 4;
    int tx = t & 15, ty = t >> 4;

    for (int k0 = 0; k0 < 512; k0 += 8) {
        int ao = o0 + arow;
        float4 a4 = make_float4(0.f, 0.f, 0.f, 0.f);
        if (ao < 704) a4 = *(const float4*)&g_Wall[ao * 512 + k0 + akq];
        float4 b4 = *(const float4*)&B[(size_t)(k0 + bk) * NPIX + n0 + bnq];
        __syncthreads();
        As[akq + 0][arow] = a4.x; As[akq + 1][arow] = a4.y;
        As[akq + 2][arow] = a4.z; As[akq + 3][arow] = a4.w;
        *(float4*)&Bs[bk][bnq] = b4;
        __syncthreads();
#pragma unroll
        for (int k = 0; k < 8; k++) {
            float a[8], bb[8];
            *(float4*)&a[0]  = *(float4*)&As[k][ty * 8];
            *(float4*)&a[4]  = *(float4*)&As[k][ty * 8 + 4];
            *(float4*)&bb[0] = *(float4*)&Bs[k][tx * 8];
            *(float4*)&bb[4] = *(float4*)&Bs[k][tx * 8 + 4];
#pragma unroll
            for (int i = 0; i < 8; i++)
#pragma unroll
                for (int j = 0; j < 8; j++) acc[i][j] += a[i] * bb[j];
        }
    }
#pragma unroll
    for (int i = 0; i < 8; i++) {
        int o = o0 + ty * 8 + i;
        if (o >= 704) continue;
        float bias = g_ball[o];
        float* dst;
        if (o < 64)       dst = g_q + ((size_t)b * DK  + o)        * NPIX;
        else if (o < 128) dst = g_k + ((size_t)b * DK  + (o - 64)) * NPIX;
        else if (o < 640) dst = g_v + ((size_t)b * CIN + (o - 128)) * NPIX;
        else              dst = g_p + ((size_t)b * DK  + (o - 640)) * NPIX;
#pragma unroll
        for (int j = 0; j < 8; j++) dst[n0 + tx * 8 + j] = acc[i][j] + bias;
    }
}

// ---------------- energy GEMM: E[i,j] = sum_d q[d,i] * k[d,j] ----------------
__global__ __launch_bounds__(256) void energy_kernel() {
    int b = blockIdx.z;
    int j0 = blockIdx.x * 128;
    int i0 = blockIdx.y * 128;
    const float* q  = g_q + (size_t)b * DK * NPIX;
    const float* kk = g_k + (size_t)b * DK * NPIX;

    __shared__ float Qs[8][128];
    __shared__ float Ks[8][128];
    int t = threadIdx.x;
    float acc[8][8] = {};
    int lk = t >> 5, lq = (t & 31) * 4;
    int tx = t & 15, ty = t >> 4;

    for (int d0 = 0; d0 < DK; d0 += 8) {
        float4 qa = *(const float4*)&q [(size_t)(d0 + lk) * NPIX + i0 + lq];
        float4 ka = *(const float4*)&kk[(size_t)(d0 + lk) * NPIX + j0 + lq];
        __syncthreads();
        *(float4*)&Qs[lk][lq] = qa;
        *(float4*)&Ks[lk][lq] = ka;
        __syncthreads();
#pragma unroll
        for (int k = 0; k < 8; k++) {
            float a[8], bb[8];
            *(float4*)&a[0]  = *(float4*)&Qs[k][ty * 8];
            *(float4*)&a[4]  = *(float4*)&Qs[k][ty * 8 + 4];
            *(float4*)&bb[0] = *(float4*)&Ks[k][tx * 8];
            *(float4*)&bb[4] = *(float4*)&Ks[k][tx * 8 + 4];
#pragma unroll
            for (int i = 0; i < 8; i++)
#pragma unroll
                for (int j = 0; j < 8; j++) acc[i][j] += a[i] * bb[j];
        }
    }
#pragma unroll
    for (int i = 0; i < 8; i++) {
        int ii = i0 + ty * 8 + i;
        float* row = &g_attn[((size_t)b * NPIX + ii) * NPIX + j0 + tx * 8];
        *(float4*)&row[0] = make_float4(acc[i][0], acc[i][1], acc[i][2], acc[i][3]);
        *(float4*)&row[4] = make_float4(acc[i][4], acc[i][5], acc[i][6], acc[i][7]);
    }
}

// ---------------- row softmax over N=4096, in-place on g_attn ----------------
__device__ __forceinline__ float blkRedMax(float v, float* red) {
#pragma unroll
    for (int o = 16; o > 0; o >>= 1) v = fmaxf(v, __shfl_xor_sync(0xffffffffu, v, o));
    if ((threadIdx.x & 31) == 0) red[threadIdx.x >> 5] = v;
    __syncthreads();
    float r = (threadIdx.x < 8) ? red[threadIdx.x] : -1e30f;
    if (threadIdx.x < 32) {
#pragma unroll
        for (int o = 4; o > 0; o >>= 1) r = fmaxf(r, __shfl_xor_sync(0xffffffffu, r, o));
        if (threadIdx.x == 0) red[0] = r;
    }
    __syncthreads();
    float res = red[0];
    __syncthreads();
    return res;
}
__device__ __forceinline__ float blkRedSum(float v, float* red) {
#pragma unroll
    for (int o = 16; o > 0; o >>= 1) v += __shfl_xor_sync(0xffffffffu, v, o);
    if ((threadIdx.x & 31) == 0) red[threadIdx.x >> 5] = v;
    __syncthreads();
    float r = (threadIdx.x < 8) ? red[threadIdx.x] : 0.f;
    if (threadIdx.x < 32) {
#pragma unroll
        for (int o = 4; o > 0; o >>= 1) r += __shfl_xor_sync(0xffffffffu, r, o);
        if (threadIdx.x == 0) red[0] = r;
    }
    __syncthreads();
    float res = red[0];
    __syncthreads();
    return res;
}

__global__ __launch_bounds__(256) void softmax_kernel() {
    int i = blockIdx.x, b = blockIdx.y;
    float* row = g_attn + ((size_t)b * NPIX + i) * NPIX;
    int t = threadIdx.x;
    __shared__ float red[8];

    float4 v[4];
    float mx = -1e30f;
#pragma unroll
    for (int j = 0; j < 4; j++) {
        v[j] = *(float4*)&row[t * 4 + 1024 * j];
        mx = fmaxf(mx, fmaxf(fmaxf(v[j].x, v[j].y), fmaxf(v[j].z, v[j].w)));
    }
    float rmax = blkRedMax(mx, red);
    float s = 0.f;
#pragma unroll
    for (int j = 0; j < 4; j++) {
        v[j].x = __expf(v[j].x - rmax); v[j].y = __expf(v[j].y - rmax);
        v[j].z = __expf(v[j].z - rmax); v[j].w = __expf(v[j].w - rmax);
        s += v[j].x + v[j].y + v[j].z + v[j].w;
    }
    float inv = 1.f / blkRedSum(s, red);
#pragma unroll
    for (int j = 0; j < 4; j++) {
        v[j].x *= inv; v[j].y *= inv; v[j].z *= inv; v[j].w *= inv;
        *(float4*)&row[t * 4 + 1024 * j] = v[j];
    }
}

// ---------------- s_out GEMM (NT): C[c,m] = sum_n v[c,n] * attn[m,n]; out = gs*C + x ----------------
__global__ __launch_bounds__(256) void sout_kernel(const float* __restrict__ x,
                                                   const float* __restrict__ gamma_s,
                                                   float* __restrict__ out) {
    int b = blockIdx.z;
    int m0 = blockIdx.x * 128;
    int c0 = blockIdx.y * 128;
    const float* A  = g_v    + (size_t)b * CIN * NPIX;
    const float* Bm = g_attn + (size_t)b * NPIX * NPIX;

    __shared__ float As[8][128];
    __shared__ float Bs[8][128];
    int t = threadIdx.x;
    float acc[8][8] = {};
    int arow = t >> 1, akq = (t & 1) * 4;
    int tx = t & 15, ty = t >> 4;

    for (int k0 = 0; k0 < NPIX; k0 += 8) {
        float4 a4 = *(const float4*)&A [(size_t)(c0 + arow) * NPIX + k0 + akq];
        float4 b4 = *(const float4*)&Bm[(size_t)(m0 + arow) * NPIX + k0 + akq];
        __syncthreads();
        As[akq + 0][arow] = a4.x; As[akq + 1][arow] = a4.y;
        As[akq + 2][arow] = a4.z; As[akq + 3][arow] = a4.w;
        Bs[akq + 0][arow] = b4.x; Bs[akq + 1][arow] = b4.y;
        Bs[akq + 2][arow] = b4.z; Bs[akq + 3][arow] = b4.w;
        __syncthreads();
#pragma unroll
        for (int k = 0; k < 8; k++) {
            float a[8], bb[8];
            *(float4*)&a[0]  = *(float4*)&As[k][ty * 8];
            *(float4*)&a[4]  = *(float4*)&As[k][ty * 8 + 4];
            *(float4*)&bb[0] = *(float4*)&Bs[k][tx * 8];
            *(float4*)&bb[4] = *(float4*)&Bs[k][tx * 8 + 4];
#pragma unroll
            for (int i = 0; i < 8; i++)
#pragma unroll
                for (int j = 0; j < 8; j++) acc[i][j] += a[i] * bb[j];
        }
    }
    float gs = *gamma_s;
    const float* xb = x   + (size_t)b * CIN * NPIX;
    float*       ob = out + (size_t)b * CIN * NPIX;
#pragma unroll
    for (int i = 0; i < 8; i++) {
        int c = c0 + ty * 8 + i;
        size_t base = (size_t)c * NPIX + m0 + tx * 8;
        float4 x0 = *(const float4*)&xb[base];
        float4 x1 = *(const float4*)&xb[base + 4];
        float4 o0 = make_float4(gs * acc[i][0] + x0.x, gs * acc[i][1] + x0.y,
                                gs * acc[i][2] + x0.z, gs * acc[i][3] + x0.w);
        float4 o1 = make_float4(gs * acc[i][4] + x1.x, gs * acc[i][5] + x1.y,
                                gs * acc[i][6] + x1.z, gs * acc[i][7] + x1.w);
        *(float4*)&ob[base]     = o0;
        *(float4*)&ob[base + 4] = o1;
    }
}

// ---------------- channel path ----------------
// e partials: each block sums a 512-wide K slice of e[c,d] = p[c,:].p[d,:]
__global__ __launch_bounds__(256) void chan_e_kernel() {
    int b = blockIdx.y, kb = blockIdx.x;
    const float* p = g_p + (size_t)b * DK * NPIX;
    __shared__ float sp[64][65];   // sp[k][channel]
    int t = threadIdx.x;
    int tx = t & 15, ty = t >> 4;
    float acc[4][4] = {};
    for (int ch = 0; ch < 8; ch++) {
        int base = kb * 512 + ch * 64;
        __syncthreads();
#pragma unroll
        for (int i = 0; i < 16; i++) {
            int lin = t + 256 * i;
            int r = lin >> 6, c = lin & 63;
            sp[c][r] = p[(size_t)r * NPIX + base + c];
        }
        __syncthreads();
#pragma unroll 8
        for (int k = 0; k < 64; k++) {
            float a[4], bb[4];
#pragma unroll
            for (int i = 0; i < 4; i++) a[i]  = sp[k][ty * 4 + i];
#pragma unroll
            for (int j = 0; j < 4; j++) bb[j] = sp[k][tx * 4 + j];
#pragma unroll
            for (int i = 0; i < 4; i++)
#pragma unroll
                for (int j = 0; j < 4; j++) acc[i][j] += a[i] * bb[j];
        }
    }
#pragma unroll
    for (int i = 0; i < 4; i++)
#pragma unroll
        for (int j = 0; j < 4; j++)
            g_epart[(((size_t)kb * BAT + b) * DK + ty * 4 + i) * DK + tx * 4 + j] = acc[i][j];
}

// softmax(max_d(e) - e) per row; exp(min - e)/sum trick (numerically identical)
__global__ void chan_softmax_kernel() {
    int b = blockIdx.x;
    int t = threadIdx.x, w = t >> 5, lane = t & 31;
    for (int r = w * 8; r < w * 8 + 8; r++) {
        float v0 = 0.f, v1 = 0.f;
#pragma unroll
        for (int kb = 0; kb < 8; kb++) {
            const float* ep = &g_epart[(((size_t)kb * BAT + b) * DK + r) * DK];
            v0 += ep[lane];
            v1 += ep[lane + 32];
        }
        float mn = fminf(v0, v1);
#pragma unroll
        for (int o = 16; o > 0; o >>= 1) mn = fminf(mn, __shfl_xor_sync(0xffffffffu, mn, o));
        float z0 = __expf(mn - v0), z1 = __expf(mn - v1);
        float s = z0 + z1;
#pragma unroll
        for (int o = 16; o > 0; o >>= 1) s += __shfl_xor_sync(0xffffffffu, s, o);
        float inv = 1.f / s;
        g_cattn[((size_t)b * DK + r) * DK + lane]      = z0 * inv;
        g_cattn[((size_t)b * DK + r) * DK + lane + 32] = z1 * inv;
    }
}

// c_fused[c,n] = gamma_c * (sum_d cattn[c,d] * p[d,n]) + p[c,n]
__global__ __launch_bounds__(256) void chan_out_kernel(const float* __restrict__ gamma_c) {
    int b = blockIdx.y;
    int n0 = blockIdx.x * 64;
    const float* p = g_p + (size_t)b * DK * NPIX;
    __shared__ float at[64][65];   // at[d][c]
    __shared__ float sp[64][64];   // sp[d][n]
    int t = threadIdx.x;
    int tx = t & 15, ty = t >> 4;
#pragma unroll
    for (int i = 0; i < 16; i++) {
        int lin = t + 256 * i;
        int c = lin >> 6, d = lin & 63;
        at[d][c] = g_cattn[(size_t)b * DK * DK + lin];
    }
#pragma unroll
    for (int i = 0; i < 16; i++) {
        int lin = t + 256 * i;
        int r = lin >> 6, c = lin & 63;
        sp[r][c] = p[(size_t)r * NPIX + n0 + c];
    }
    __syncthreads();
    float acc[4][4] = {};
#pragma unroll 8
    for (int k = 0; k < 64; k++) {
        float a[4], bb[4];
#pragma unroll
        for (int i = 0; i < 4; i++) a[i]  = at[k][ty * 4 + i];
#pragma unroll
        for (int j = 0; j < 4; j++) bb[j] = sp[k][tx * 4 + j];
#pragma unroll
        for (int i = 0; i < 4; i++)
#pragma unroll
            for (int j = 0; j < 4; j++) acc[i][j] += a[i] * bb[j];
    }
    float gc = *gamma_c;
#pragma unroll
    for (int i = 0; i < 4; i++) {
        int c = ty * 4 + i;
#pragma unroll
        for (int j = 0; j < 4; j++) {
            int n = tx * 4 + j;
            g_cf[((size_t)b * DK + c) * NPIX + n0 + n] = gc * acc[i][j] + sp[c][n];
        }
    }
}

// ---------------- final: out += Wu @ cf + bu ----------------
__global__ __launch_bounds__(256) void final_kernel(const float* __restrict__ Wu,
                                                    const float* __restrict__ bu,
                                                    float* __restrict__ out) {
    int b = blockIdx.z;
    int n0 = blockIdx.x * 128;
    int o0 = blockIdx.y * 128;
    const float* cf = g_cf + (size_t)b * DK * NPIX;

    __shared__ float As[8][128];
    __shared__ float Bs[8][128];
    int t = threadIdx.x;
    float acc[8][8] = {};
    int arow = t >> 1, akq = (t & 1) * 4;
    int bk = t >> 5, bnq = (t & 31) * 4;
    int tx = t & 15, ty = t >> 4;

    for (int k0 = 0; k0 < DK; k0 += 8) {
        float4 a4 = *(const float4*)&Wu[(o0 + arow) * DK + k0 + akq];
        float4 b4 = *(const float4*)&cf[(size_t)(k0 + bk) * NPIX + n0 + bnq];
        __syncthreads();
        As[akq + 0][arow] = a4.x; As[akq + 1][arow] = a4.y;
        As[akq + 2][arow] = a4.z; As[akq + 3][arow] = a4.w;
        *(float4*)&Bs[bk][bnq] = b4;
        __syncthreads();
#pragma unroll
        for (int k = 0; k < 8; k++) {
            float a[8], bb[8];
            *(float4*)&a[0]  = *(float4*)&As[k][ty * 8];
            *(float4*)&a[4]  = *(float4*)&As[k][ty * 8 + 4];
            *(float4*)&bb[0] = *(float4*)&Bs[k][tx * 8];
            *(float4*)&bb[4] = *(float4*)&Bs[k][tx * 8 + 4];
#pragma unroll
            for (int i = 0; i < 8; i++)
#pragma unroll
                for (int j = 0; j < 8; j++) acc[i][j] += a[i] * bb[j];
        }
    }
#pragma unroll
    for (int i = 0; i < 8; i++) {
        int o = o0 + ty * 8 + i;
        float bias = bu[o];
        size_t base = ((size_t)b * CIN + o) * NPIX + n0 + tx * 8;
        float4 c0 = *(float4*)&out[base];
        float4 c1 = *(float4*)&out[base + 4];
        c0.x += acc[i][0] + bias; c0.y += acc[i][1] + bias;
        c0.z += acc[i][2] + bias; c0.w += acc[i][3] + bias;
        c1.x += acc[i][4] + bias; c1.y += acc[i][5] + bias;
        c1.z += acc[i][6] + bias; c1.w += acc[i][7] + bias;
        *(float4*)&out[base]     = c0;
        *(float4*)&out[base + 4] = c1;
    }
}

// ---------------- launch ----------------
extern "C" void kernel_launch(void* const* d_in, const int* in_sizes, int n_in,
                              void* d_out, int out_size) {
    const float* x  = (const float*)d_in[0];
    const float* Wq = (const float*)d_in[1];
    const float* bq = (const float*)d_in[2];
    const float* Wk = (const float*)d_in[3];
    const float* bk = (const float*)d_in[4];
    const float* Wv = (const float*)d_in[5];
    const float* bv = (const float*)d_in[6];
    const float* gs = (const float*)d_in[7];
    const float* Wd = (const float*)d_in[8];
    const float* bd = (const float*)d_in[9];
    const float* Wu = (const float*)d_in[10];
    const float* bu = (const float*)d_in[11];
    const float* gc = (const float*)d_in[12];
    float* out = (float*)d_out;

    pack_kernel<<<(704 * 512 + 255) / 256, 256>>>(Wq, bq, Wk, bk, Wv, bv, Wd, bd);
    proj_kernel<<<dim3(32, 6, BAT), 256>>>(x);
    energy_kernel<<<dim3(32, 32, BAT), 256>>>();
    softmax_kernel<<<dim3(NPIX, BAT), 256>>>();
    sout_kernel<<<dim3(32, 4, BAT), 256>>>(x, gs, out);
    chan_e_kernel<<<dim3(8, BAT), 256>>>();
    chan_softmax_kernel<<<BAT, 256>>>();
    chan_out_kernel<<<dim3(64, BAT), 256>>>(gc);
    final_kernel<<<dim3(32, 4, BAT), 256>>>(Wu, bu, out);
}

// round 6
// speedup vs baseline: 1.3333x; 1.3333x over previous
#include <cuda_runtime.h>
#include <cuda_bf16.h>
#include <cstdint>

#define NPIX 4096
#define CIN  512
#define DK   64
#define BAT  4

// ---------------- scratch (device globals; no runtime allocation) ----------------
__device__ float g_q[BAT * DK * NPIX];
__device__ float g_k[BAT * DK * NPIX];
__device__ float g_p[BAT * DK * NPIX];          // xd
__device__ float g_cf[BAT * DK * NPIX];         // gamma_c * c_out + xd
__device__ float g_attn[(size_t)BAT * NPIX * NPIX];            // fp32 energy (pre-softmax)
__device__ __nv_bfloat16 g_attnh[(size_t)BAT * NPIX * NPIX];   // attn hi
__device__ __nv_bfloat16 g_attnl[(size_t)BAT * NPIX * NPIX];   // attn lo (residual)
__device__ __nv_bfloat16 g_vh[BAT * CIN * NPIX];               // v hi
__device__ __nv_bfloat16 g_vl[BAT * CIN * NPIX];               // v lo
__device__ float g_Wall[704 * 512];
__device__ float g_ball[704];
__device__ float g_epart[8 * BAT * DK * DK];
__device__ float g_cattn[BAT * DK * DK];

// ---------------- helpers ----------------
__device__ __forceinline__ uint32_t smem_u32(const void* p) {
    uint32_t a;
    asm("{ .reg .u64 t; cvta.to.shared.u64 t, %1; cvt.u32.u64 %0, t; }" : "=r"(a) : "l"(p));
    return a;
}
__device__ __forceinline__ void ldm_x4(uint32_t r[4], uint32_t addr) {
    asm volatile("ldmatrix.sync.aligned.m8n8.x4.shared.b16 {%0,%1,%2,%3}, [%4];"
                 : "=r"(r[0]), "=r"(r[1]), "=r"(r[2]), "=r"(r[3]) : "r"(addr));
}
__device__ __forceinline__ void mma16816(float c[4], const uint32_t a[4], uint32_t b0, uint32_t b1) {
    asm volatile("mma.sync.aligned.m16n8k16.row.col.f32.bf16.bf16.f32 "
                 "{%0,%1,%2,%3}, {%4,%5,%6,%7}, {%8,%9}, {%0,%1,%2,%3};"
                 : "+f"(c[0]), "+f"(c[1]), "+f"(c[2]), "+f"(c[3])
                 : "r"(a[0]), "r"(a[1]), "r"(a[2]), "r"(a[3]), "r"(b0), "r"(b1));
}
__device__ __forceinline__ void split_bf16(float x, __nv_bfloat16& h, __nv_bfloat16& l) {
    h = __float2bfloat16(x);
    l = __float2bfloat16(x - __bfloat162float(h));
}

// ---------------- weight packing ----------------
__global__ void pack_kernel(const float* __restrict__ Wq, const float* __restrict__ bq,
                            const float* __restrict__ Wk, const float* __restrict__ bk,
                            const float* __restrict__ Wv, const float* __restrict__ bv,
                            const float* __restrict__ Wd, const float* __restrict__ bd) {
    int i = blockIdx.x * blockDim.x + threadIdx.x;
    if (i < 704 * 512) {
        int o = i >> 9, c = i & 511;
        float v;
        if (o < 64)        v = Wq[o * 512 + c];
        else if (o < 128)  v = Wk[(o - 64) * 512 + c];
        else if (o < 640)  v = Wv[(o - 128) * 512 + c];
        else               v = Wd[(o - 640) * 512 + c];
        g_Wall[i] = v;
    }
    if (i < 704) {
        float v;
        if (i < 64)        v = bq[i];
        else if (i < 128)  v = bk[i - 64];
        else if (i < 640)  v = bv[i - 128];
        else               v = bd[i - 640];
        g_ball[i] = v;
    }
}

// ---------------- projection GEMM ----------------
__global__ __launch_bounds__(256) void proj_kernel(const float* __restrict__ x) {
    int b = blockIdx.z;
    int n0 = blockIdx.x * 128;
    int o0 = blockIdx.y * 128;
    const float* B = x + (size_t)b * CIN * NPIX;

    __shared__ float As[8][128];
    __shared__ float Bs[8][128];
    int t = threadIdx.x;
    float acc[8][8] = {};
    int arow = t >> 1, akq = (t & 1) * 4;
    int bk = t >> 5, bnq = (t & 31) * 4;
    int tx = t & 15, ty = t >> 4;

    for (int k0 = 0; k0 < 512; k0 += 8) {
        int ao = o0 + arow;
        float4 a4 = make_float4(0.f, 0.f, 0.f, 0.f);
        if (ao < 704) a4 = *(const float4*)&g_Wall[ao * 512 + k0 + akq];
        float4 b4 = *(const float4*)&B[(size_t)(k0 + bk) * NPIX + n0 + bnq];
        __syncthreads();
        As[akq + 0][arow] = a4.x; As[akq + 1][arow] = a4.y;
        As[akq + 2][arow] = a4.z; As[akq + 3][arow] = a4.w;
        *(float4*)&Bs[bk][bnq] = b4;
        __syncthreads();
#pragma unroll
        for (int k = 0; k < 8; k++) {
            float a[8], bb[8];
            *(float4*)&a[0]  = *(float4*)&As[k][ty * 8];
            *(float4*)&a[4]  = *(float4*)&As[k][ty * 8 + 4];
            *(float4*)&bb[0] = *(float4*)&Bs[k][tx * 8];
            *(float4*)&bb[4] = *(float4*)&Bs[k][tx * 8 + 4];
#pragma unroll
            for (int i = 0; i < 8; i++)
#pragma unroll
                for (int j = 0; j < 8; j++) acc[i][j] += a[i] * bb[j];
        }
    }
#pragma unroll
    for (int i = 0; i < 8; i++) {
        int o = o0 + ty * 8 + i;
        if (o >= 704) continue;
        float bias = g_ball[o];
        if (o >= 128 && o < 640) {
            size_t off = ((size_t)b * CIN + (o - 128)) * NPIX + n0 + tx * 8;
            __nv_bfloat16 h[8], l[8];
#pragma unroll
            for (int j = 0; j < 8; j++) split_bf16(acc[i][j] + bias, h[j], l[j]);
            *(uint4*)(g_vh + off) = *(uint4*)h;
            *(uint4*)(g_vl + off) = *(uint4*)l;
        } else {
            float* dst;
            if (o < 64)       dst = g_q + ((size_t)b * DK + o) * NPIX;
            else if (o < 128) dst = g_k + ((size_t)b * DK + (o - 64)) * NPIX;
            else              dst = g_p + ((size_t)b * DK + (o - 640)) * NPIX;
#pragma unroll
            for (int j = 0; j < 8; j++) dst[n0 + tx * 8 + j] = acc[i][j] + bias;
        }
    }
}

// ---------------- energy GEMM (fp32) ----------------
__global__ __launch_bounds__(256) void energy_kernel() {
    int b = blockIdx.z;
    int j0 = blockIdx.x * 128;
    int i0 = blockIdx.y * 128;
    const float* q  = g_q + (size_t)b * DK * NPIX;
    const float* kk = g_k + (size_t)b * DK * NPIX;

    __shared__ float Qs[8][128];
    __shared__ float Ks[8][128];
    int t = threadIdx.x;
    float acc[8][8] = {};
    int lk = t >> 5, lq = (t & 31) * 4;
    int tx = t & 15, ty = t >> 4;

    for (int d0 = 0; d0 < DK; d0 += 8) {
        float4 qa = *(const float4*)&q [(size_t)(d0 + lk) * NPIX + i0 + lq];
        float4 ka = *(const float4*)&kk[(size_t)(d0 + lk) * NPIX + j0 + lq];
        __syncthreads();
        *(float4*)&Qs[lk][lq] = qa;
        *(float4*)&Ks[lk][lq] = ka;
        __syncthreads();
#pragma unroll
        for (int k = 0; k < 8; k++) {
            float a[8], bb[8];
            *(float4*)&a[0]  = *(float4*)&Qs[k][ty * 8];
            *(float4*)&a[4]  = *(float4*)&Qs[k][ty * 8 + 4];
            *(float4*)&bb[0] = *(float4*)&Ks[k][tx * 8];
            *(float4*)&bb[4] = *(float4*)&Ks[k][tx * 8 + 4];
#pragma unroll
            for (int i = 0; i < 8; i++)
#pragma unroll
                for (int j = 0; j < 8; j++) acc[i][j] += a[i] * bb[j];
        }
    }
#pragma unroll
    for (int i = 0; i < 8; i++) {
        int ii = i0 + ty * 8 + i;
        float* row = &g_attn[((size_t)b * NPIX + ii) * NPIX + j0 + tx * 8];
        *(float4*)&row[0] = make_float4(acc[i][0], acc[i][1], acc[i][2], acc[i][3]);
        *(float4*)&row[4] = make_float4(acc[i][4], acc[i][5], acc[i][6], acc[i][7]);
    }
}

// ---------------- softmax: fp32 in, split bf16 out ----------------
__device__ __forceinline__ float blkRedMax(float v, float* red) {
#pragma unroll
    for (int o = 16; o > 0; o >>= 1) v = fmaxf(v, __shfl_xor_sync(0xffffffffu, v, o));
    if ((threadIdx.x & 31) == 0) red[threadIdx.x >> 5] = v;
    __syncthreads();
    float r = (threadIdx.x < 8) ? red[threadIdx.x] : -1e30f;
    if (threadIdx.x < 32) {
#pragma unroll
        for (int o = 4; o > 0; o >>= 1) r = fmaxf(r, __shfl_xor_sync(0xffffffffu, r, o));
        if (threadIdx.x == 0) red[0] = r;
    }
    __syncthreads();
    float res = red[0];
    __syncthreads();
    return res;
}
__device__ __forceinline__ float blkRedSum(float v, float* red) {
#pragma unroll
    for (int o = 16; o > 0; o >>= 1) v += __shfl_xor_sync(0xffffffffu, v, o);
    if ((threadIdx.x & 31) == 0) red[threadIdx.x >> 5] = v;
    __syncthreads();
    float r = (threadIdx.x < 8) ? red[threadIdx.x] : 0.f;
    if (threadIdx.x < 32) {
#pragma unroll
        for (int o = 4; o > 0; o >>= 1) r += __shfl_xor_sync(0xffffffffu, r, o);
        if (threadIdx.x == 0) red[0] = r;
    }
    __syncthreads();
    float res = red[0];
    __syncthreads();
    return res;
}

__global__ __launch_bounds__(256) void softmax_kernel() {
    int i = blockIdx.x, b = blockIdx.y;
    const float* row = g_attn + ((size_t)b * NPIX + i) * NPIX;
    __nv_bfloat16* oh = g_attnh + ((size_t)b * NPIX + i) * NPIX;
    __nv_bfloat16* ol = g_attnl + ((size_t)b * NPIX + i) * NPIX;
    int t = threadIdx.x;
    __shared__ float red[8];

    float4 v[4];
    float mx = -1e30f;
#pragma unroll
    for (int j = 0; j < 4; j++) {
        v[j] = *(const float4*)&row[t * 4 + 1024 * j];
        mx = fmaxf(mx, fmaxf(fmaxf(v[j].x, v[j].y), fmaxf(v[j].z, v[j].w)));
    }
    float rmax = blkRedMax(mx, red);
    float s = 0.f;
#pragma unroll
    for (int j = 0; j < 4; j++) {
        v[j].x = __expf(v[j].x - rmax); v[j].y = __expf(v[j].y - rmax);
        v[j].z = __expf(v[j].z - rmax); v[j].w = __expf(v[j].w - rmax);
        s += v[j].x + v[j].y + v[j].z + v[j].w;
    }
    float inv = 1.f / blkRedSum(s, red);
#pragma unroll
    for (int j = 0; j < 4; j++) {
        __nv_bfloat16 h[4], l[4];
        split_bf16(v[j].x * inv, h[0], l[0]);
        split_bf16(v[j].y * inv, h[1], l[1]);
        split_bf16(v[j].z * inv, h[2], l[2]);
        split_bf16(v[j].w * inv, h[3], l[3]);
        *(uint2*)&oh[t * 4 + 1024 * j] = *(uint2*)h;
        *(uint2*)&ol[t * 4 + 1024 * j] = *(uint2*)l;
    }
}

// ---------------- s_out via split-bf16 mma.sync (3-term product) ----------------
// C[c,m] = sum_n v[c,n] * attn[m,n]; out = gamma_s*C + x
// smem tiles stored [row][k] row-major = col-major KxN for the B operand
// => B fragments use NON-trans ldmatrix (trans would block-transpose B).
#define SSTRIDE 40
#define TILE_B  (128 * SSTRIDE * 2)   // 10240 bytes per bf16 tile
__global__ __launch_bounds__(256, 2) void sout_mma_kernel(const float* __restrict__ x,
                                                          const float* __restrict__ gamma_s,
                                                          float* __restrict__ out) {
    extern __shared__ __align__(16) char smem[];
    // layout: [buf][Ah, Al, Bh, Bl] each TILE_B
    uint32_t sbase = smem_u32(smem);

    int b = blockIdx.z;
    int m0 = blockIdx.x * 128;
    int c0 = blockIdx.y * 128;
    int t = threadIdx.x, lane = t & 31, wid = t >> 5;
    int warpM = wid & 3, warpN = wid >> 2;

    const __nv_bfloat16* vh = g_vh    + (size_t)b * CIN  * NPIX;
    const __nv_bfloat16* vl = g_vl    + (size_t)b * CIN  * NPIX;
    const __nv_bfloat16* ah = g_attnh + (size_t)b * NPIX * NPIX;
    const __nv_bfloat16* al = g_attnl + (size_t)b * NPIX * NPIX;

    float acc[2][8][4] = {};

    int arow0 = t >> 2,          ac0 = (t & 3) * 8;
    int arow1 = (t + 256) >> 2,  ac1 = ((t + 256) & 3) * 8;

    uint4 sAh0, sAh1, sAl0, sAl1, sBh0, sBh1, sBl0, sBl1;
#define GLOAD(k0) do { \
        sAh0 = *(const uint4*)(vh + (size_t)(c0 + arow0) * NPIX + (k0) + ac0); \
        sAh1 = *(const uint4*)(vh + (size_t)(c0 + arow1) * NPIX + (k0) + ac1); \
        sAl0 = *(const uint4*)(vl + (size_t)(c0 + arow0) * NPIX + (k0) + ac0); \
        sAl1 = *(const uint4*)(vl + (size_t)(c0 + arow1) * NPIX + (k0) + ac1); \
        sBh0 = *(const uint4*)(ah + (size_t)(m0 + arow0) * NPIX + (k0) + ac0); \
        sBh1 = *(const uint4*)(ah + (size_t)(m0 + arow1) * NPIX + (k0) + ac1); \
        sBl0 = *(const uint4*)(al + (size_t)(m0 + arow0) * NPIX + (k0) + ac0); \
        sBl1 = *(const uint4*)(al + (size_t)(m0 + arow1) * NPIX + (k0) + ac1); \
    } while (0)
#define SSTORE(buf) do { \
        uint32_t o0_ = (uint32_t)(arow0 * SSTRIDE + ac0) * 2; \
        uint32_t o1_ = (uint32_t)(arow1 * SSTRIDE + ac1) * 2; \
        uint32_t bo_ = (uint32_t)(buf) * (4 * TILE_B); \
        *(uint4*)(smem + bo_ + 0 * TILE_B + o0_) = sAh0; \
        *(uint4*)(smem + bo_ + 0 * TILE_B + o1_) = sAh1; \
        *(uint4*)(smem + bo_ + 1 * TILE_B + o0_) = sAl0; \
        *(uint4*)(smem + bo_ + 1 * TILE_B + o1_) = sAl1; \
        *(uint4*)(smem + bo_ + 2 * TILE_B + o0_) = sBh0; \
        *(uint4*)(smem + bo_ + 2 * TILE_B + o1_) = sBh1; \
        *(uint4*)(smem + bo_ + 3 * TILE_B + o0_) = sBl0; \
        *(uint4*)(smem + bo_ + 3 * TILE_B + o1_) = sBl1; \
    } while (0)

    int lrow = lane & 15, lhalf = lane >> 4;

    GLOAD(0);
    SSTORE(0);
    __syncthreads();

    for (int kb = 0; kb < 128; kb++) {
        int buf = kb & 1;
        if (kb < 127) GLOAD((kb + 1) * 32);

        uint32_t tb = sbase + buf * (4 * TILE_B);
        uint32_t aH = tb, aL = tb + TILE_B, bH = tb + 2 * TILE_B, bL = tb + 3 * TILE_B;
#pragma unroll
        for (int ks = 0; ks < 2; ks++) {
            uint32_t ah_fr[2][4], al_fr[2][4];
#pragma unroll
            for (int mi = 0; mi < 2; mi++) {
                int row = warpM * 32 + mi * 16 + lrow;
                uint32_t off = row * (SSTRIDE * 2) + ks * 32 + lhalf * 16;
                ldm_x4(ah_fr[mi], aH + off);
                ldm_x4(al_fr[mi], aL + off);
            }
#pragma unroll
            for (int ng = 0; ng < 4; ng++) {
                int row = warpN * 64 + ng * 16 + lrow;
                uint32_t off = row * (SSTRIDE * 2) + ks * 32 + lhalf * 16;
                uint32_t bh_fr[4], bl_fr[4];
                ldm_x4(bh_fr, bH + off);   // non-trans: [m][k] tile == col-major KxN
                ldm_x4(bl_fr, bL + off);
#pragma unroll
                for (int mi = 0; mi < 2; mi++) {
                    mma16816(acc[mi][2 * ng],     ah_fr[mi], bh_fr[0], bh_fr[2]);
                    mma16816(acc[mi][2 * ng],     ah_fr[mi], bl_fr[0], bl_fr[2]);
                    mma16816(acc[mi][2 * ng],     al_fr[mi], bh_fr[0], bh_fr[2]);
                    mma16816(acc[mi][2 * ng + 1], ah_fr[mi], bh_fr[1], bh_fr[3]);
                    mma16816(acc[mi][2 * ng + 1], ah_fr[mi], bl_fr[1], bl_fr[3]);
                    mma16816(acc[mi][2 * ng + 1], al_fr[mi], bh_fr[1], bh_fr[3]);
                }
            }
        }
        __syncthreads();
        if (kb < 127) {
            SSTORE((kb + 1) & 1);
            __syncthreads();
        }
    }

    // epilogue
    float gs = *gamma_s;
    const float* xb = x   + (size_t)b * CIN * NPIX;
    float*       ob = out + (size_t)b * CIN * NPIX;
#pragma unroll
    for (int mi = 0; mi < 2; mi++) {
        int row = c0 + warpM * 32 + mi * 16 + (lane >> 2);
#pragma unroll
        for (int ni = 0; ni < 8; ni++) {
            int col = m0 + warpN * 64 + ni * 8 + (lane & 3) * 2;
            size_t i0 = (size_t)row * NPIX + col;
            float2 x0 = *(const float2*)&xb[i0];
            float2 o0 = make_float2(gs * acc[mi][ni][0] + x0.x, gs * acc[mi][ni][1] + x0.y);
            *(float2*)&ob[i0] = o0;
            size_t i1 = i0 + (size_t)8 * NPIX;
            float2 x1 = *(const float2*)&xb[i1];
            float2 o1 = make_float2(gs * acc[mi][ni][2] + x1.x, gs * acc[mi][ni][3] + x1.y);
            *(float2*)&ob[i1] = o1;
        }
    }
}

// ---------------- channel path ----------------
__global__ __launch_bounds__(256) void chan_e_kernel() {
    int b = blockIdx.y, kb = blockIdx.x;
    const float* p = g_p + (size_t)b * DK * NPIX;
    __shared__ float sp[64][65];
    int t = threadIdx.x;
    int tx = t & 15, ty = t >> 4;
    float acc[4][4] = {};
    for (int ch = 0; ch < 8; ch++) {
        int base = kb * 512 + ch * 64;
        __syncthreads();
#pragma unroll
        for (int i = 0; i < 16; i++) {
            int lin = t + 256 * i;
            int r = lin >> 6, c = lin & 63;
            sp[c][r] = p[(size_t)r * NPIX + base + c];
        }
        __syncthreads();
#pragma unroll 8
        for (int k = 0; k < 64; k++) {
            float a[4], bb[4];
#pragma unroll
            for (int i = 0; i < 4; i++) a[i]  = sp[k][ty * 4 + i];
#pragma unroll
            for (int j = 0; j < 4; j++) bb[j] = sp[k][tx * 4 + j];
#pragma unroll
            for (int i = 0; i < 4; i++)
#pragma unroll
                for (int j = 0; j < 4; j++) acc[i][j] += a[i] * bb[j];
        }
    }
#pragma unroll
    for (int i = 0; i < 4; i++)
#pragma unroll
        for (int j = 0; j < 4; j++)
            g_epart[(((size_t)kb * BAT + b) * DK + ty * 4 + i) * DK + tx * 4 + j] = acc[i][j];
}

__global__ void chan_softmax_kernel() {
    int b = blockIdx.x;
    int t = threadIdx.x, w = t >> 5, lane = t & 31;
    for (int r = w * 8; r < w * 8 + 8; r++) {
        float v0 = 0.f, v1 = 0.f;
#pragma unroll
        for (int kb = 0; kb < 8; kb++) {
            const float* ep = &g_epart[(((size_t)kb * BAT + b) * DK + r) * DK];
            v0 += ep[lane];
            v1 += ep[lane + 32];
        }
        float mn = fminf(v0, v1);
#pragma unroll
        for (int o = 16; o > 0; o >>= 1) mn = fminf(mn, __shfl_xor_sync(0xffffffffu, mn, o));
        float z0 = __expf(mn - v0), z1 = __expf(mn - v1);
        float s = z0 + z1;
#pragma unroll
        for (int o = 16; o > 0; o >>= 1) s += __shfl_xor_sync(0xffffffffu, s, o);
        float inv = 1.f / s;
        g_cattn[((size_t)b * DK + r) * DK + lane]      = z0 * inv;
        g_cattn[((size_t)b * DK + r) * DK + lane + 32] = z1 * inv;
    }
}

__global__ __launch_bounds__(256) void chan_out_kernel(const float* __restrict__ gamma_c) {
    int b = blockIdx.y;
    int n0 = blockIdx.x * 64;
    const float* p = g_p + (size_t)b * DK * NPIX;
    __shared__ float at[64][65];
    __shared__ float sp[64][64];
    int t = threadIdx.x;
    int tx = t & 15, ty = t >> 4;
#pragma unroll
    for (int i = 0; i < 16; i++) {
        int lin = t + 256 * i;
        int c = lin >> 6, d = lin & 63;
        at[d][c] = g_cattn[(size_t)b * DK * DK + lin];
    }
#pragma unroll
    for (int i = 0; i < 16; i++) {
        int lin = t + 256 * i;
        int r = lin >> 6, c = lin & 63;
        sp[r][c] = p[(size_t)r * NPIX + n0 + c];
    }
    __syncthreads();
    float acc[4][4] = {};
#pragma unroll 8
    for (int k = 0; k < 64; k++) {
        float a[4], bb[4];
#pragma unroll
        for (int i = 0; i < 4; i++) a[i]  = at[k][ty * 4 + i];
#pragma unroll
        for (int j = 0; j < 4; j++) bb[j] = sp[k][tx * 4 + j];
#pragma unroll
        for (int i = 0; i < 4; i++)
#pragma unroll
            for (int j = 0; j < 4; j++) acc[i][j] += a[i] * bb[j];
    }
    float gc = *gamma_c;
#pragma unroll
    for (int i = 0; i < 4; i++) {
        int c = ty * 4 + i;
#pragma unroll
        for (int j = 0; j < 4; j++) {
            int n = tx * 4 + j;
            g_cf[((size_t)b * DK + c) * NPIX + n0 + n] = gc * acc[i][j] + sp[c][n];
        }
    }
}

// ---------------- final: out += Wu @ cf + bu ----------------
__global__ __launch_bounds__(256) void final_kernel(const float* __restrict__ Wu,
                                                    const float* __restrict__ bu,
                                                    float* __restrict__ out) {
    int b = blockIdx.z;
    int n0 = blockIdx.x * 128;
    int o0 = blockIdx.y * 128;
    const float* cf = g_cf + (size_t)b * DK * NPIX;

    __shared__ float As[8][128];
    __shared__ float Bs[8][128];
    int t = threadIdx.x;
    float acc[8][8] = {};
    int arow = t >> 1, akq = (t & 1) * 4;
    int bk = t >> 5, bnq = (t & 31) * 4;
    int tx = t & 15, ty = t >> 4;

    for (int k0 = 0; k0 < DK; k0 += 8) {
        float4 a4 = *(const float4*)&Wu[(o0 + arow) * DK + k0 + akq];
        float4 b4 = *(const float4*)&cf[(size_t)(k0 + bk) * NPIX + n0 + bnq];
        __syncthreads();
        As[akq + 0][arow] = a4.x; As[akq + 1][arow] = a4.y;
        As[akq + 2][arow] = a4.z; As[akq + 3][arow] = a4.w;
        *(float4*)&Bs[bk][bnq] = b4;
        __syncthreads();
#pragma unroll
        for (int k = 0; k < 8; k++) {
            float a[8], bb[8];
            *(float4*)&a[0]  = *(float4*)&As[k][ty * 8];
            *(float4*)&a[4]  = *(float4*)&As[k][ty * 8 + 4];
            *(float4*)&bb[0] = *(float4*)&Bs[k][tx * 8];
            *(float4*)&bb[4] = *(float4*)&Bs[k][tx * 8 + 4];
#pragma unroll
            for (int i = 0; i < 8; i++)
#pragma unroll
                for (int j = 0; j < 8; j++) acc[i][j] += a[i] * bb[j];
        }
    }
#pragma unroll
    for (int i = 0; i < 8; i++) {
        int o = o0 + ty * 8 + i;
        float bias = bu[o];
        size_t base = ((size_t)b * CIN + o) * NPIX + n0 + tx * 8;
        float4 c0 = *(float4*)&out[base];
        float4 c1 = *(float4*)&out[base + 4];
        c0.x += acc[i][0] + bias; c0.y += acc[i][1] + bias;
        c0.z += acc[i][2] + bias; c0.w += acc[i][3] + bias;
        c1.x += acc[i][4] + bias; c1.y += acc[i][5] + bias;
        c1.z += acc[i][6] + bias; c1.w += acc[i][7] + bias;
        *(float4*)&out[base]     = c0;
        *(float4*)&out[base + 4] = c1;
    }
}

// ---------------- launch ----------------
extern "C" void kernel_launch(void* const* d_in, const int* in_sizes, int n_in,
                              void* d_out, int out_size) {
    const float* x  = (const float*)d_in[0];
    const float* Wq = (const float*)d_in[1];
    const float* bq = (const float*)d_in[2];
    const float* Wk = (const float*)d_in[3];
    const float* bk = (const float*)d_in[4];
    const float* Wv = (const float*)d_in[5];
    const float* bv = (const float*)d_in[6];
    const float* gs = (const float*)d_in[7];
    const float* Wd = (const float*)d_in[8];
    const float* bd = (const float*)d_in[9];
    const float* Wu = (const float*)d_in[10];
    const float* bu = (const float*)d_in[11];
    const float* gc = (const float*)d_in[12];
    float* out = (float*)d_out;

    const int SOUT_SMEM = 8 * TILE_B;  // 81920 bytes
    cudaFuncSetAttribute(sout_mma_kernel, cudaFuncAttributeMaxDynamicSharedMemorySize, SOUT_SMEM);

    pack_kernel<<<(704 * 512 + 255) / 256, 256>>>(Wq, bq, Wk, bk, Wv, bv, Wd, bd);
    proj_kernel<<<dim3(32, 6, BAT), 256>>>(x);
    energy_kernel<<<dim3(32, 32, BAT), 256>>>();
    softmax_kernel<<<dim3(NPIX, BAT), 256>>>();
    sout_mma_kernel<<<dim3(32, 4, BAT), 256, SOUT_SMEM>>>(x, gs, out);
    chan_e_kernel<<<dim3(8, BAT), 256>>>();
    chan_softmax_kernel<<<BAT, 256>>>();
    chan_out_kernel<<<dim3(64, BAT), 256>>>(gc);
    final_kernel<<<dim3(32, 4, BAT), 256>>>(Wu, bu, out);
}

// round 7
// speedup vs baseline: 4.4158x; 3.3120x over previous
#include <cuda_runtime.h>
#include <cuda_bf16.h>
#include <cstdint>

#define NPIX 4096
#define CIN  512
#define DK   64
#define BAT  4

// ---------------- scratch (device globals; no runtime allocation) ----------------
__device__ __nv_bfloat16 g_qb[BAT * DK * NPIX];     // q bf16 [b][d][n]
__device__ __nv_bfloat16 g_kb[BAT * DK * NPIX];     // k bf16 [b][d][n]
__device__ __nv_bfloat16 g_vbf[BAT * CIN * NPIX];   // v bf16 [b][c][n]
__device__ float g_p[BAT * DK * NPIX];              // xd fp32 (channel path, undamped)
__device__ float g_cf[BAT * DK * NPIX];
__device__ float g_attn[(size_t)BAT * NPIX * NPIX];           // fp32 energy
__device__ __nv_bfloat16 g_attnb[(size_t)BAT * NPIX * NPIX];  // bf16 attn
__device__ __nv_bfloat16 g_Wb[640 * 512];           // [Wq;Wk;Wv] bf16
__device__ float g_ball[640];
__device__ __nv_bfloat16 g_xh[BAT * CIN * NPIX];    // x bf16
__device__ float g_epart[8 * BAT * DK * DK];
__device__ float g_cattn[BAT * DK * DK];

// ---------------- helpers ----------------
__device__ __forceinline__ uint32_t smem_u32(const void* p) {
    uint32_t a;
    asm("{ .reg .u64 t; cvta.to.shared.u64 t, %1; cvt.u32.u64 %0, t; }" : "=r"(a) : "l"(p));
    return a;
}
__device__ __forceinline__ void ldm_x4(uint32_t r[4], uint32_t addr) {
    asm volatile("ldmatrix.sync.aligned.m8n8.x4.shared.b16 {%0,%1,%2,%3}, [%4];"
                 : "=r"(r[0]), "=r"(r[1]), "=r"(r[2]), "=r"(r[3]) : "r"(addr));
}
__device__ __forceinline__ void ldm_x4t(uint32_t r[4], uint32_t addr) {
    asm volatile("ldmatrix.sync.aligned.m8n8.x4.trans.shared.b16 {%0,%1,%2,%3}, [%4];"
                 : "=r"(r[0]), "=r"(r[1]), "=r"(r[2]), "=r"(r[3]) : "r"(addr));
}
__device__ __forceinline__ void mma16816(float c[4], const uint32_t a[4], uint32_t b0, uint32_t b1) {
    asm volatile("mma.sync.aligned.m16n8k16.row.col.f32.bf16.bf16.f32 "
                 "{%0,%1,%2,%3}, {%4,%5,%6,%7}, {%8,%9}, {%0,%1,%2,%3};"
                 : "+f"(c[0]), "+f"(c[1]), "+f"(c[2]), "+f"(c[3])
                 : "r"(a[0]), "r"(a[1]), "r"(a[2]), "r"(a[3]), "r"(b0), "r"(b1));
}
__device__ __forceinline__ void cp16(uint32_t dst, const void* src) {
    asm volatile("cp.async.cg.shared.global [%0], [%1], 16;" :: "r"(dst), "l"(src) : "memory");
}
#define CP_COMMIT() asm volatile("cp.async.commit_group;" ::: "memory")
#define CP_WAIT1()  asm volatile("cp.async.wait_group 1;" ::: "memory")
#define CP_WAIT0()  asm volatile("cp.async.wait_group 0;" ::: "memory")

// ---------------- weight pack (fp32 -> bf16) + bias ----------------
__global__ void pack_kernel(const float* __restrict__ Wq, const float* __restrict__ bq,
                            const float* __restrict__ Wk, const float* __restrict__ bk,
                            const float* __restrict__ Wv, const float* __restrict__ bv) {
    int i = blockIdx.x * blockDim.x + threadIdx.x;
    if (i < 640 * 512) {
        int o = i >> 9, c = i & 511;
        float v;
        if (o < 64)       v = Wq[o * 512 + c];
        else if (o < 128) v = Wk[(o - 64) * 512 + c];
        else              v = Wv[(o - 128) * 512 + c];
        g_Wb[i] = __float2bfloat16(v);
    }
    if (i < 640) {
        float v;
        if (i < 64)       v = bq[i];
        else if (i < 128) v = bk[i - 64];
        else              v = bv[i - 128];
        g_ball[i] = v;
    }
}

// ---------------- x -> bf16 ----------------
__global__ void xcvt_kernel(const float* __restrict__ x) {
    int idx = blockIdx.x * blockDim.x + threadIdx.x;
    float4 v = *(const float4*)&x[(size_t)idx * 4];
    __nv_bfloat162 h0 = __floats2bfloat162_rn(v.x, v.y);
    __nv_bfloat162 h1 = __floats2bfloat162_rn(v.z, v.w);
    uint2 pk;
    pk.x = *(uint32_t*)&h0; pk.y = *(uint32_t*)&h1;
    *(uint2*)&g_xh[(size_t)idx * 4] = pk;
}

// ---------------- proj q/k/v via bf16 HMMA ----------------
// out[o][n] = sum_c W[o][c] x[c][n] + bias; o in [0,640)
#define PW_STRIDE 72
#define PX_STRIDE 136
#define PW_BYTES (128 * PW_STRIDE * 2)   // 18432
#define PX_BYTES (64 * PX_STRIDE * 2)    // 17408
#define PSTAGE   (PW_BYTES + PX_BYTES)   // 35840
__global__ __launch_bounds__(256) void projqkv_kernel() {
    extern __shared__ __align__(16) char smem[];
    uint32_t sb = smem_u32(smem);
    int b = blockIdx.z;
    int n0 = blockIdx.x * 128;
    int o0 = blockIdx.y * 128;
    int t = threadIdx.x, lane = t & 31, wid = t >> 5;
    int warpM = wid & 3, warpN = wid >> 2;
    int lrow = lane & 15, lhalf = lane >> 4;
    const __nv_bfloat16* xb = g_xh + (size_t)b * CIN * NPIX;
    float acc[2][8][4] = {};

#define PQ_ISSUE(kb) do { \
        uint32_t base = sb + ((kb) & 1) * PSTAGE; \
        for (int it = 0; it < 4; it++) { \
            int g = t + it * 256; \
            int row = g >> 3, cc = (g & 7) * 8; \
            cp16(base + row * (PW_STRIDE * 2) + cc * 2, \
                 g_Wb + (size_t)(o0 + row) * 512 + (kb) * 64 + cc); \
        } \
        for (int it = 0; it < 4; it++) { \
            int g = t + it * 256; \
            int row = g >> 4, cc = (g & 15) * 8; \
            cp16(base + PW_BYTES + row * (PX_STRIDE * 2) + cc * 2, \
                 xb + (size_t)((kb) * 64 + row) * NPIX + n0 + cc); \
        } \
        CP_COMMIT(); \
    } while (0)

    PQ_ISSUE(0);
    int dbase = ((lane >> 4) << 3) + (lane & 7);
    int coladd = ((lane >> 3) & 1) * 8;
    for (int kb = 0; kb < 8; kb++) {
        if (kb < 7) { PQ_ISSUE(kb + 1); CP_WAIT1(); } else CP_WAIT0();
        __syncthreads();
        uint32_t base = sb + (kb & 1) * PSTAGE;
        uint32_t wB = base, xB = base + PW_BYTES;
#pragma unroll
        for (int ks = 0; ks < 4; ks++) {
            uint32_t afr[2][4];
#pragma unroll
            for (int mi = 0; mi < 2; mi++) {
                int row = warpM * 32 + mi * 16 + lrow;
                ldm_x4(afr[mi], wB + row * (PW_STRIDE * 2) + ks * 32 + lhalf * 16);
            }
            int drow = ks * 16 + dbase;
#pragma unroll
            for (int ng = 0; ng < 4; ng++) {
                uint32_t bfr[4];
                ldm_x4t(bfr, xB + drow * (PX_STRIDE * 2) + (warpN * 64 + ng * 16 + coladd) * 2);
#pragma unroll
                for (int mi = 0; mi < 2; mi++) {
                    mma16816(acc[mi][2 * ng],     afr[mi], bfr[0], bfr[2]);
                    mma16816(acc[mi][2 * ng + 1], afr[mi], bfr[1], bfr[3]);
                }
            }
        }
        __syncthreads();
    }
    // epilogue: bias + bf16, scatter to q/k/v
#pragma unroll
    for (int mi = 0; mi < 2; mi++) {
        int row_lo = o0 + warpM * 32 + mi * 16 + (lane >> 2);
        int row_hi = row_lo + 8;
        float bl = g_ball[row_lo], bh = g_ball[row_hi];
        __nv_bfloat16* dlo;
        __nv_bfloat16* dhi;
        if (row_lo < 64)       dlo = g_qb + ((size_t)b * DK + row_lo) * NPIX;
        else if (row_lo < 128) dlo = g_kb + ((size_t)b * DK + row_lo - 64) * NPIX;
        else                   dlo = g_vbf + ((size_t)b * CIN + row_lo - 128) * NPIX;
        if (row_hi < 64)       dhi = g_qb + ((size_t)b * DK + row_hi) * NPIX;
        else if (row_hi < 128) dhi = g_kb + ((size_t)b * DK + row_hi - 64) * NPIX;
        else                   dhi = g_vbf + ((size_t)b * CIN + row_hi - 128) * NPIX;
#pragma unroll
        for (int ni = 0; ni < 8; ni++) {
            int col = (blockIdx.x * 128) + warpN * 64 + ni * 8 + (lane & 3) * 2;
            __nv_bfloat162 h0 = __floats2bfloat162_rn(acc[mi][ni][0] + bl, acc[mi][ni][1] + bl);
            __nv_bfloat162 h1 = __floats2bfloat162_rn(acc[mi][ni][2] + bh, acc[mi][ni][3] + bh);
            *(uint32_t*)(dlo + col) = *(uint32_t*)&h0;
            *(uint32_t*)(dhi + col) = *(uint32_t*)&h1;
        }
    }
}

// ---------------- proj p (xd) fp32 ----------------
__global__ __launch_bounds__(256) void proj_p_kernel(const float* __restrict__ x,
                                                     const float* __restrict__ Wd,
                                                     const float* __restrict__ bd) {
    int b = blockIdx.z;
    int n0 = blockIdx.x * 128;
    const float* B = x + (size_t)b * CIN * NPIX;
    __shared__ float As[8][64];
    __shared__ float Bs[8][128];
    int t = threadIdx.x;
    int tx = t & 15, ty = t >> 4;
    float acc[4][8] = {};
    for (int k0 = 0; k0 < 512; k0 += 8) {
        float4 a4 = make_float4(0.f, 0.f, 0.f, 0.f);
        int arow = t >> 1, akq = (t & 1) * 4;
        if (t < 128) a4 = *(const float4*)&Wd[arow * 512 + k0 + akq];
        int bk = t >> 5, bnq = (t & 31) * 4;
        float4 b4 = *(const float4*)&B[(size_t)(k0 + bk) * NPIX + n0 + bnq];
        __syncthreads();
        if (t < 128) {
            As[akq + 0][arow] = a4.x; As[akq + 1][arow] = a4.y;
            As[akq + 2][arow] = a4.z; As[akq + 3][arow] = a4.w;
        }
        *(float4*)&Bs[bk][bnq] = b4;
        __syncthreads();
#pragma unroll
        for (int k = 0; k < 8; k++) {
            float a[4], bb[8];
#pragma unroll
            for (int i = 0; i < 4; i++) a[i] = As[k][ty * 4 + i];
            *(float4*)&bb[0] = *(float4*)&Bs[k][tx * 8];
            *(float4*)&bb[4] = *(float4*)&Bs[k][tx * 8 + 4];
#pragma unroll
            for (int i = 0; i < 4; i++)
#pragma unroll
                for (int j = 0; j < 8; j++) acc[i][j] += a[i] * bb[j];
        }
    }
#pragma unroll
    for (int i = 0; i < 4; i++) {
        int row = ty * 4 + i;
        float bias = bd[row];
        float* dst = g_p + ((size_t)b * DK + row) * NPIX + n0 + tx * 8;
#pragma unroll
        for (int j = 0; j < 8; j++) dst[j] = acc[i][j] + bias;
    }
}

// ---------------- energy via bf16 HMMA ----------------
// E[i,j] = sum_d q[d,i] k[d,j]; q/k stored [d][n] -> trans ldmatrix for both operands
__global__ __launch_bounds__(256) void energy_hmma_kernel() {
    __shared__ __align__(16) __nv_bfloat16 Qs[64 * 136];
    __shared__ __align__(16) __nv_bfloat16 Ks[64 * 136];
    int b = blockIdx.z, j0 = blockIdx.x * 128, i0 = blockIdx.y * 128;
    int t = threadIdx.x, lane = t & 31, wid = t >> 5;
    int warpM = wid & 3, warpN = wid >> 2;
    const __nv_bfloat16* qp = g_qb + (size_t)b * DK * NPIX;
    const __nv_bfloat16* kp = g_kb + (size_t)b * DK * NPIX;
    uint32_t sQ = smem_u32(Qs), sK = smem_u32(Ks);
#pragma unroll
    for (int it = 0; it < 4; it++) {
        int g = t + it * 256;
        int row = g >> 4, cc = (g & 15) * 8;
        cp16(sQ + row * 272 + cc * 2, qp + (size_t)row * NPIX + i0 + cc);
        cp16(sK + row * 272 + cc * 2, kp + (size_t)row * NPIX + j0 + cc);
    }
    CP_COMMIT();
    CP_WAIT0();
    __syncthreads();

    float acc[2][8][4] = {};
    int dbase = ((lane >> 4) << 3) + (lane & 7);
    int coladd = ((lane >> 3) & 1) * 8;
#pragma unroll
    for (int ks = 0; ks < 4; ks++) {
        int drow = ks * 16 + dbase;
        uint32_t afr[2][4];
#pragma unroll
        for (int mi = 0; mi < 2; mi++)
            ldm_x4t(afr[mi], sQ + drow * 272 + (warpM * 32 + mi * 16 + coladd) * 2);
#pragma unroll
        for (int ng = 0; ng < 4; ng++) {
            uint32_t bfr[4];
            ldm_x4t(bfr, sK + drow * 272 + (warpN * 64 + ng * 16 + coladd) * 2);
#pragma unroll
            for (int mi = 0; mi < 2; mi++) {
                mma16816(acc[mi][2 * ng],     afr[mi], bfr[0], bfr[2]);
                mma16816(acc[mi][2 * ng + 1], afr[mi], bfr[1], bfr[3]);
            }
        }
    }
    float* Eb = g_attn + (size_t)b * NPIX * NPIX;
#pragma unroll
    for (int mi = 0; mi < 2; mi++) {
        int row = i0 + warpM * 32 + mi * 16 + (lane >> 2);
#pragma unroll
        for (int ni = 0; ni < 8; ni++) {
            int col = j0 + warpN * 64 + ni * 8 + (lane & 3) * 2;
            *(float2*)&Eb[(size_t)row * NPIX + col]       = make_float2(acc[mi][ni][0], acc[mi][ni][1]);
            *(float2*)&Eb[(size_t)(row + 8) * NPIX + col] = make_float2(acc[mi][ni][2], acc[mi][ni][3]);
        }
    }
}

// ---------------- softmax: fp32 in, bf16 out ----------------
__device__ __forceinline__ float blkRedMax(float v, float* red) {
#pragma unroll
    for (int o = 16; o > 0; o >>= 1) v = fmaxf(v, __shfl_xor_sync(0xffffffffu, v, o));
    if ((threadIdx.x & 31) == 0) red[threadIdx.x >> 5] = v;
    __syncthreads();
    float r = (threadIdx.x < 8) ? red[threadIdx.x] : -1e30f;
    if (threadIdx.x < 32) {
#pragma unroll
        for (int o = 4; o > 0; o >>= 1) r = fmaxf(r, __shfl_xor_sync(0xffffffffu, r, o));
        if (threadIdx.x == 0) red[0] = r;
    }
    __syncthreads();
    float res = red[0];
    __syncthreads();
    return res;
}
__device__ __forceinline__ float blkRedSum(float v, float* red) {
#pragma unroll
    for (int o = 16; o > 0; o >>= 1) v += __shfl_xor_sync(0xffffffffu, v, o);
    if ((threadIdx.x & 31) == 0) red[threadIdx.x >> 5] = v;
    __syncthreads();
    float r = (threadIdx.x < 8) ? red[threadIdx.x] : 0.f;
    if (threadIdx.x < 32) {
#pragma unroll
        for (int o = 4; o > 0; o >>= 1) r += __shfl_xor_sync(0xffffffffu, r, o);
        if (threadIdx.x == 0) red[0] = r;
    }
    __syncthreads();
    float res = red[0];
    __syncthreads();
    return res;
}

__global__ __launch_bounds__(256) void softmax_kernel() {
    int i = blockIdx.x, b = blockIdx.y;
    const float* row = g_attn + ((size_t)b * NPIX + i) * NPIX;
    __nv_bfloat16* orow = g_attnb + ((size_t)b * NPIX + i) * NPIX;
    int t = threadIdx.x;
    __shared__ float red[8];

    float4 v[4];
    float mx = -1e30f;
#pragma unroll
    for (int j = 0; j < 4; j++) {
        v[j] = *(const float4*)&row[t * 4 + 1024 * j];
        mx = fmaxf(mx, fmaxf(fmaxf(v[j].x, v[j].y), fmaxf(v[j].z, v[j].w)));
    }
    float rmax = blkRedMax(mx, red);
    float s = 0.f;
#pragma unroll
    for (int j = 0; j < 4; j++) {
        v[j].x = __expf(v[j].x - rmax); v[j].y = __expf(v[j].y - rmax);
        v[j].z = __expf(v[j].z - rmax); v[j].w = __expf(v[j].w - rmax);
        s += v[j].x + v[j].y + v[j].z + v[j].w;
    }
    float inv = 1.f / blkRedSum(s, red);
#pragma unroll
    for (int j = 0; j < 4; j++) {
        __nv_bfloat162 h0 = __floats2bfloat162_rn(v[j].x * inv, v[j].y * inv);
        __nv_bfloat162 h1 = __floats2bfloat162_rn(v[j].z * inv, v[j].w * inv);
        uint2 pk;
        pk.x = *(uint32_t*)&h0; pk.y = *(uint32_t*)&h1;
        *(uint2*)&orow[t * 4 + 1024 * j] = pk;
    }
}

// ---------------- s_out single-pass bf16 HMMA + cp.async pipeline ----------------
// C[c,m] = sum_n v[c,n] attn[m,n]; out = gamma_s*C + x
#define SO_STRIDE 72
#define SO_TILE   (128 * SO_STRIDE * 2)   // 18432
#define SO_STAGE  (2 * SO_TILE)           // 36864
__global__ __launch_bounds__(256) void sout_kernel(const float* __restrict__ x,
                                                   const float* __restrict__ gamma_s,
                                                   float* __restrict__ out) {
    extern __shared__ __align__(16) char smem[];
    uint32_t sb = smem_u32(smem);
    int b = blockIdx.z;
    int m0 = blockIdx.x * 128;
    int c0 = blockIdx.y * 128;
    int t = threadIdx.x, lane = t & 31, wid = t >> 5;
    int warpM = wid & 3, warpN = wid >> 2;
    int lrow = lane & 15, lhalf = lane >> 4;
    const __nv_bfloat16* vb = g_vbf   + (size_t)b * CIN  * NPIX;
    const __nv_bfloat16* ab = g_attnb + (size_t)b * NPIX * NPIX;
    float acc[2][8][4] = {};

#define SO_ISSUE(kb) do { \
        uint32_t base = sb + ((kb) & 1) * SO_STAGE; \
        for (int it = 0; it < 4; it++) { \
            int g = t + it * 256; \
            int row = g >> 3, cc = (g & 7) * 8; \
            cp16(base + row * (SO_STRIDE * 2) + cc * 2, \
                 vb + (size_t)(c0 + row) * NPIX + (kb) * 64 + cc); \
        } \
        for (int it = 0; it < 4; it++) { \
            int g = t + it * 256; \
            int row = g >> 3, cc = (g & 7) * 8; \
            cp16(base + SO_TILE + row * (SO_STRIDE * 2) + cc * 2, \
                 ab + (size_t)(m0 + row) * NPIX + (kb) * 64 + cc); \
        } \
        CP_COMMIT(); \
    } while (0)

    SO_ISSUE(0);
    for (int kb = 0; kb < 64; kb++) {
        if (kb < 63) { SO_ISSUE(kb + 1); CP_WAIT1(); } else CP_WAIT0();
        __syncthreads();
        uint32_t base = sb + (kb & 1) * SO_STAGE;
        uint32_t aB = base, bB = base + SO_TILE;
#pragma unroll
        for (int ks = 0; ks < 4; ks++) {
            uint32_t afr[2][4];
#pragma unroll
            for (int mi = 0; mi < 2; mi++) {
                int row = warpM * 32 + mi * 16 + lrow;
                ldm_x4(afr[mi], aB + row * (SO_STRIDE * 2) + ks * 32 + lhalf * 16);
            }
#pragma unroll
            for (int ng = 0; ng < 4; ng++) {
                int row = warpN * 64 + ng * 16 + lrow;
                uint32_t bfr[4];
                ldm_x4(bfr, bB + row * (SO_STRIDE * 2) + ks * 32 + lhalf * 16);
#pragma unroll
                for (int mi = 0; mi < 2; mi++) {
                    mma16816(acc[mi][2 * ng],     afr[mi], bfr[0], bfr[2]);
                    mma16816(acc[mi][2 * ng + 1], afr[mi], bfr[1], bfr[3]);
                }
            }
        }
        __syncthreads();
    }

    float gs = *gamma_s;
    const float* xb = x   + (size_t)b * CIN * NPIX;
    float*       ob = out + (size_t)b * CIN * NPIX;
#pragma unroll
    for (int mi = 0; mi < 2; mi++) {
        int row = c0 + warpM * 32 + mi * 16 + (lane >> 2);
#pragma unroll
        for (int ni = 0; ni < 8; ni++) {
            int col = m0 + warpN * 64 + ni * 8 + (lane & 3) * 2;
            size_t i0 = (size_t)row * NPIX + col;
            float2 x0 = *(const float2*)&xb[i0];
            float2 o0 = make_float2(gs * acc[mi][ni][0] + x0.x, gs * acc[mi][ni][1] + x0.y);
            *(float2*)&ob[i0] = o0;
            size_t i1 = i0 + (size_t)8 * NPIX;
            float2 x1 = *(const float2*)&xb[i1];
            float2 o1 = make_float2(gs * acc[mi][ni][2] + x1.x, gs * acc[mi][ni][3] + x1.y);
            *(float2*)&ob[i1] = o1;
        }
    }
}

// ---------------- channel path (fp32, undamped -> keep precise) ----------------
__global__ __launch_bounds__(256) void chan_e_kernel() {
    int b = blockIdx.y, kb = blockIdx.x;
    const float* p = g_p + (size_t)b * DK * NPIX;
    __shared__ float sp[64][65];
    int t = threadIdx.x;
    int tx = t & 15, ty = t >> 4;
    float acc[4][4] = {};
    for (int ch = 0; ch < 8; ch++) {
        int base = kb * 512 + ch * 64;
        __syncthreads();
#pragma unroll
        for (int i = 0; i < 16; i++) {
            int lin = t + 256 * i;
            int r = lin >> 6, c = lin & 63;
            sp[c][r] = p[(size_t)r * NPIX + base + c];
        }
        __syncthreads();
#pragma unroll 8
        for (int k = 0; k < 64; k++) {
            float a[4], bb[4];
#pragma unroll
            for (int i = 0; i < 4; i++) a[i]  = sp[k][ty * 4 + i];
#pragma unroll
            for (int j = 0; j < 4; j++) bb[j] = sp[k][tx * 4 + j];
#pragma unroll
            for (int i = 0; i < 4; i++)
#pragma unroll
                for (int j = 0; j < 4; j++) acc[i][j] += a[i] * bb[j];
        }
    }
#pragma unroll
    for (int i = 0; i < 4; i++)
#pragma unroll
        for (int j = 0; j < 4; j++)
            g_epart[(((size_t)kb * BAT + b) * DK + ty * 4 + i) * DK + tx * 4 + j] = acc[i][j];
}

__global__ void chan_softmax_kernel() {
    int b = blockIdx.x;
    int t = threadIdx.x, w = t >> 5, lane = t & 31;
    for (int r = w * 8; r < w * 8 + 8; r++) {
        float v0 = 0.f, v1 = 0.f;
#pragma unroll
        for (int kb = 0; kb < 8; kb++) {
            const float* ep = &g_epart[(((size_t)kb * BAT + b) * DK + r) * DK];
            v0 += ep[lane];
            v1 += ep[lane + 32];
        }
        float mn = fminf(v0, v1);
#pragma unroll
        for (int o = 16; o > 0; o >>= 1) mn = fminf(mn, __shfl_xor_sync(0xffffffffu, mn, o));
        float z0 = __expf(mn - v0), z1 = __expf(mn - v1);
        float s = z0 + z1;
#pragma unroll
        for (int o = 16; o > 0; o >>= 1) s += __shfl_xor_sync(0xffffffffu, s, o);
        float inv = 1.f / s;
        g_cattn[((size_t)b * DK + r) * DK + lane]      = z0 * inv;
        g_cattn[((size_t)b * DK + r) * DK + lane + 32] = z1 * inv;
    }
}

__global__ __launch_bounds__(256) void chan_out_kernel(const float* __restrict__ gamma_c) {
    int b = blockIdx.y;
    int n0 = blockIdx.x * 64;
    const float* p = g_p + (size_t)b * DK * NPIX;
    __shared__ float at[64][65];
    __shared__ float sp[64][64];
    int t = threadIdx.x;
    int tx = t & 15, ty = t >> 4;
#pragma unroll
    for (int i = 0; i < 16; i++) {
        int lin = t + 256 * i;
        int c = lin >> 6, d = lin & 63;
        at[d][c] = g_cattn[(size_t)b * DK * DK + lin];
    }
#pragma unroll
    for (int i = 0; i < 16; i++) {
        int lin = t + 256 * i;
        int r = lin >> 6, c = lin & 63;
        sp[r][c] = p[(size_t)r * NPIX + n0 + c];
    }
    __syncthreads();
    float acc[4][4] = {};
#pragma unroll 8
    for (int k = 0; k < 64; k++) {
        float a[4], bb[4];
#pragma unroll
        for (int i = 0; i < 4; i++) a[i]  = at[k][ty * 4 + i];
#pragma unroll
        for (int j = 0; j < 4; j++) bb[j] = sp[k][tx * 4 + j];
#pragma unroll
        for (int i = 0; i < 4; i++)
#pragma unroll
            for (int j = 0; j < 4; j++) acc[i][j] += a[i] * bb[j];
    }
    float gc = *gamma_c;
#pragma unroll
    for (int i = 0; i < 4; i++) {
        int c = ty * 4 + i;
#pragma unroll
        for (int j = 0; j < 4; j++) {
            int n = tx * 4 + j;
            g_cf[((size_t)b * DK + c) * NPIX + n0 + n] = gc * acc[i][j] + sp[c][n];
        }
    }
}

// ---------------- final: out += Wu @ cf + bu ----------------
__global__ __launch_bounds__(256) void final_kernel(const float* __restrict__ Wu,
                                                    const float* __restrict__ bu,
                                                    float* __restrict__ out) {
    int b = blockIdx.z;
    int n0 = blockIdx.x * 128;
    int o0 = blockIdx.y * 128;
    const float* cf = g_cf + (size_t)b * DK * NPIX;

    __shared__ float As[8][128];
    __shared__ float Bs[8][128];
    int t = threadIdx.x;
    float acc[8][8] = {};
    int arow = t >> 1, akq = (t & 1) * 4;
    int bk = t >> 5, bnq = (t & 31) * 4;
    int tx = t & 15, ty = t >> 4;

    for (int k0 = 0; k0 < DK; k0 += 8) {
        float4 a4 = *(const float4*)&Wu[(o0 + arow) * DK + k0 + akq];
        float4 b4 = *(const float4*)&cf[(size_t)(k0 + bk) * NPIX + n0 + bnq];
        __syncthreads();
        As[akq + 0][arow] = a4.x; As[akq + 1][arow] = a4.y;
        As[akq + 2][arow] = a4.z; As[akq + 3][arow] = a4.w;
        *(float4*)&Bs[bk][bnq] = b4;
        __syncthreads();
#pragma unroll
        for (int k = 0; k < 8; k++) {
            float a[8], bb[8];
            *(float4*)&a[0]  = *(float4*)&As[k][ty * 8];
            *(float4*)&a[4]  = *(float4*)&As[k][ty * 8 + 4];
            *(float4*)&bb[0] = *(float4*)&Bs[k][tx * 8];
            *(float4*)&bb[4] = *(float4*)&Bs[k][tx * 8 + 4];
#pragma unroll
            for (int i = 0; i < 8; i++)
#pragma unroll
                for (int j = 0; j < 8; j++) acc[i][j] += a[i] * bb[j];
        }
    }
#pragma unroll
    for (int i = 0; i < 8; i++) {
        int o = o0 + ty * 8 + i;
        float bias = bu[o];
        size_t base = ((size_t)b * CIN + o) * NPIX + n0 + tx * 8;
        float4 c0 = *(float4*)&out[base];
        float4 c1 = *(float4*)&out[base + 4];
        c0.x += acc[i][0] + bias; c0.y += acc[i][1] + bias;
        c0.z += acc[i][2] + bias; c0.w += acc[i][3] + bias;
        c1.x += acc[i][4] + bias; c1.y += acc[i][5] + bias;
        c1.z += acc[i][6] + bias; c1.w += acc[i][7] + bias;
        *(float4*)&out[base]     = c0;
        *(float4*)&out[base + 4] = c1;
    }
}

// ---------------- launch ----------------
extern "C" void kernel_launch(void* const* d_in, const int* in_sizes, int n_in,
                              void* d_out, int out_size) {
    const float* x  = (const float*)d_in[0];
    const float* Wq = (const float*)d_in[1];
    const float* bq = (const float*)d_in[2];
    const float* Wk = (const float*)d_in[3];
    const float* bk = (const float*)d_in[4];
    const float* Wv = (const float*)d_in[5];
    const float* bv = (const float*)d_in[6];
    const float* gs = (const float*)d_in[7];
    const float* Wd = (const float*)d_in[8];
    const float* bd = (const float*)d_in[9];
    const float* Wu = (const float*)d_in[10];
    const float* bu = (const float*)d_in[11];
    const float* gc = (const float*)d_in[12];
    float* out = (float*)d_out;

    cudaFuncSetAttribute(projqkv_kernel, cudaFuncAttributeMaxDynamicSharedMemorySize, 2 * PSTAGE);
    cudaFuncSetAttribute(sout_kernel, cudaFuncAttributeMaxDynamicSharedMemorySize, 2 * SO_STAGE);

    pack_kernel<<<(640 * 512 + 255) / 256, 256>>>(Wq, bq, Wk, bk, Wv, bv);
    xcvt_kernel<<<8192, 256>>>(x);
    proj_p_kernel<<<dim3(32, 1, BAT), 256>>>(x, Wd, bd);
    projqkv_kernel<<<dim3(32, 5, BAT), 256, 2 * PSTAGE>>>();
    energy_hmma_kernel<<<dim3(32, 32, BAT), 256>>>();
    softmax_kernel<<<dim3(NPIX, BAT), 256>>>();
    sout_kernel<<<dim3(32, 4, BAT), 256, 2 * SO_STAGE>>>(x, gs, out);
    chan_e_kernel<<<dim3(8, BAT), 256>>>();
    chan_softmax_kernel<<<BAT, 256>>>();
    chan_out_kernel<<<dim3(64, BAT), 256>>>(gc);
    final_kernel<<<dim3(32, 4, BAT), 256>>>(Wu, bu, out);
}